// round 2
// baseline (speedup 1.0000x reference)
#include <cuda_runtime.h>

// Shapes are fixed for this problem instance.
#define B_SZ 2048
#define H_SZ 2048
#define P_SZ 8192

// Scratch (no cudaMalloc allowed): proj [B, 3H] and gated [B, H]
__device__ float g_proj[(size_t)B_SZ * 3 * H_SZ];
__device__ float g_gated[(size_t)B_SZ * H_SZ];

// ---------------------------------------------------------------------------
// Kernel 1: copy conv_state -> output state region (will be partially
// overwritten by the epilogue for rows in req_pool_indices).
// ---------------------------------------------------------------------------
__global__ void copy_state_kernel(const float4* __restrict__ src,
                                  float4* __restrict__ dst, int n4) {
    int i = blockIdx.x * blockDim.x + threadIdx.x;
    int stride = gridDim.x * blockDim.x;
    for (; i < n4; i += stride) dst[i] = src[i];
}

// ---------------------------------------------------------------------------
// Kernel 2/4: C[m,n] = sum_k A[m,k] * B[n,k]
//   A: [M,K] row-major, B: [N,K] row-major, C: [M,N] row-major.
// Classic 128x128x8 block tile, 256 threads, 8x8 microtile.
// M % 128 == 0, N % 128 == 0, K % 8 == 0 guaranteed by the shapes above.
// ---------------------------------------------------------------------------
__global__ __launch_bounds__(256, 2)
void sgemm_nt_kernel(const float* __restrict__ A, const float* __restrict__ Bm,
                     float* __restrict__ C, int M, int N, int Kd) {
    const int BM = 128, BN = 128, BK = 8;
    __shared__ __align__(16) float As[BK][BM + 4];   // transposed, padded
    __shared__ __align__(16) float Bs[BK][BN + 4];

    int tid = threadIdx.x;
    int tx = tid & 15;    // n direction, 0..15
    int ty = tid >> 4;    // m direction, 0..15
    int mBase = blockIdx.y * BM;
    int nBase = blockIdx.x * BN;

    int loadRow = tid >> 1;        // 0..127
    int loadK   = (tid & 1) * 4;   // 0 or 4

    const float* Aptr = A + (size_t)(mBase + loadRow) * Kd + loadK;
    const float* Bptr = Bm + (size_t)(nBase + loadRow) * Kd + loadK;

    float acc[8][8];
#pragma unroll
    for (int i = 0; i < 8; i++)
#pragma unroll
        for (int j = 0; j < 8; j++) acc[i][j] = 0.f;

    for (int k0 = 0; k0 < Kd; k0 += BK) {
        float4 a4 = *(const float4*)(Aptr + k0);
        float4 b4 = *(const float4*)(Bptr + k0);
        As[loadK + 0][loadRow] = a4.x;
        As[loadK + 1][loadRow] = a4.y;
        As[loadK + 2][loadRow] = a4.z;
        As[loadK + 3][loadRow] = a4.w;
        Bs[loadK + 0][loadRow] = b4.x;
        Bs[loadK + 1][loadRow] = b4.y;
        Bs[loadK + 2][loadRow] = b4.z;
        Bs[loadK + 3][loadRow] = b4.w;
        __syncthreads();
#pragma unroll
        for (int kk = 0; kk < BK; kk++) {
            float4 a0 = *(const float4*)&As[kk][ty * 8];
            float4 a1 = *(const float4*)&As[kk][ty * 8 + 4];
            float4 b0 = *(const float4*)&Bs[kk][tx * 8];
            float4 b1 = *(const float4*)&Bs[kk][tx * 8 + 4];
            float ar[8] = {a0.x, a0.y, a0.z, a0.w, a1.x, a1.y, a1.z, a1.w};
            float br[8] = {b0.x, b0.y, b0.z, b0.w, b1.x, b1.y, b1.z, b1.w};
#pragma unroll
            for (int i = 0; i < 8; i++)
#pragma unroll
                for (int j = 0; j < 8; j++) acc[i][j] = fmaf(ar[i], br[j], acc[i][j]);
        }
        __syncthreads();
    }

#pragma unroll
    for (int i = 0; i < 8; i++) {
        float* Crow = C + (size_t)(mBase + ty * 8 + i) * N + nBase + tx * 8;
        *(float4*)Crow = make_float4(acc[i][0], acc[i][1], acc[i][2], acc[i][3]);
        *(float4*)(Crow + 4) = make_float4(acc[i][4], acc[i][5], acc[i][6], acc[i][7]);
    }
}

// ---------------------------------------------------------------------------
// Kernel 3: conv + gating epilogue.
// proj[b, 0:H] = B_gate, proj[b, H:2H] = C_gate, proj[b, 2H:3H] = x.
// gated[b,h] = C_gate * (c0*w0 + c1*w1 + c2*w2 + (B_gate*x)*w3)
// out_state[idx[b], h, :] = {c1, c2, B_gate*x}
// ---------------------------------------------------------------------------
__global__ void conv_epilogue_kernel(const float* __restrict__ proj,
                                     const float* __restrict__ conv_state,
                                     const int* __restrict__ idx,
                                     const float* __restrict__ conv_w,
                                     float* __restrict__ gated,
                                     float* __restrict__ out_state) {
    int i = blockIdx.x * blockDim.x + threadIdx.x;
    if (i >= B_SZ * H_SZ) return;
    int b = i >> 11;           // / H_SZ
    int h = i & (H_SZ - 1);    // % H_SZ
    int r = idx[b];

    const float* cs = conv_state + ((size_t)r * H_SZ + h) * 3;
    float c0 = cs[0], c1 = cs[1], c2 = cs[2];

    const float* prow = proj + (size_t)b * 3 * H_SZ;
    float Bg = prow[h];
    float Cg = prow[H_SZ + h];
    float x  = prow[2 * H_SZ + h];
    float Bx = Bg * x;

    const float* w = conv_w + h * 4;
    float conv_out = fmaf(c0, w[0], fmaf(c1, w[1], fmaf(c2, w[2], Bx * w[3])));

    gated[i] = Cg * conv_out;

    float* os = out_state + ((size_t)r * H_SZ + h) * 3;
    os[0] = c1;
    os[1] = c2;
    os[2] = Bx;
}

// ---------------------------------------------------------------------------
extern "C" void kernel_launch(void* const* d_in, const int* in_sizes, int n_in,
                              void* d_out, int out_size) {
    const float* hidden     = (const float*)d_in[0];
    const float* conv_state = (const float*)d_in[1];
    const int*   idx        = (const int*)d_in[2];
    const float* w_in       = (const float*)d_in[3];
    const float* w_out      = (const float*)d_in[4];
    const float* conv_w     = (const float*)d_in[5];

    float* y         = (float*)d_out;
    float* out_state = y + (size_t)B_SZ * H_SZ;

    float *proj, *gated;
    cudaGetSymbolAddress((void**)&proj, g_proj);
    cudaGetSymbolAddress((void**)&gated, g_gated);

    // 1) copy conv_state through to the output (rows later overwritten)
    int n4 = (P_SZ * H_SZ * 3) / 4;
    copy_state_kernel<<<2048, 256>>>((const float4*)conv_state,
                                     (float4*)out_state, n4);

    // 2) proj = hidden @ w_in^T   [2048 x 6144]
    sgemm_nt_kernel<<<dim3((3 * H_SZ) / 128, B_SZ / 128), 256>>>(
        hidden, w_in, proj, B_SZ, 3 * H_SZ, H_SZ);

    // 3) conv + gate epilogue, scatter new state rows
    conv_epilogue_kernel<<<(B_SZ * H_SZ + 255) / 256, 256>>>(
        proj, conv_state, idx, conv_w, gated, out_state);

    // 4) y = gated @ w_out^T   [2048 x 2048]
    sgemm_nt_kernel<<<dim3(H_SZ / 128, B_SZ / 128), 256>>>(
        gated, w_out, y, B_SZ, H_SZ, H_SZ);
}

// round 3
// speedup vs baseline: 1.0001x; 1.0001x over previous
#include <cuda_runtime.h>

// Shapes are fixed for this problem instance.
#define B_SZ 2048
#define H_SZ 2048
#define P_SZ 8192

// Scratch (no cudaMalloc allowed): proj [B, 3H] and gated [B, H]
__device__ float g_proj[(size_t)B_SZ * 3 * H_SZ];
__device__ float g_gated[(size_t)B_SZ * H_SZ];

// ---------------------------------------------------------------------------
// Kernel 1: copy conv_state -> output state region (will be partially
// overwritten by the epilogue for rows in req_pool_indices).
// ---------------------------------------------------------------------------
__global__ void copy_state_kernel(const float4* __restrict__ src,
                                  float4* __restrict__ dst, int n4) {
    int i = blockIdx.x * blockDim.x + threadIdx.x;
    int stride = gridDim.x * blockDim.x;
    for (; i < n4; i += stride) dst[i] = src[i];
}

// ---------------------------------------------------------------------------
// Kernel 2/4: C[m,n] = sum_k A[m,k] * B[n,k]
//   A: [M,K] row-major, B: [N,K] row-major, C: [M,N] row-major.
// Classic 128x128x8 block tile, 256 threads, 8x8 microtile.
// M % 128 == 0, N % 128 == 0, K % 8 == 0 guaranteed by the shapes above.
// ---------------------------------------------------------------------------
__global__ __launch_bounds__(256, 2)
void sgemm_nt_kernel(const float* __restrict__ A, const float* __restrict__ Bm,
                     float* __restrict__ C, int M, int N, int Kd) {
    const int BM = 128, BN = 128, BK = 8;
    __shared__ __align__(16) float As[BK][BM + 4];   // transposed, padded
    __shared__ __align__(16) float Bs[BK][BN + 4];

    int tid = threadIdx.x;
    int tx = tid & 15;    // n direction, 0..15
    int ty = tid >> 4;    // m direction, 0..15
    int mBase = blockIdx.y * BM;
    int nBase = blockIdx.x * BN;

    int loadRow = tid >> 1;        // 0..127
    int loadK   = (tid & 1) * 4;   // 0 or 4

    const float* Aptr = A + (size_t)(mBase + loadRow) * Kd + loadK;
    const float* Bptr = Bm + (size_t)(nBase + loadRow) * Kd + loadK;

    float acc[8][8];
#pragma unroll
    for (int i = 0; i < 8; i++)
#pragma unroll
        for (int j = 0; j < 8; j++) acc[i][j] = 0.f;

    for (int k0 = 0; k0 < Kd; k0 += BK) {
        float4 a4 = *(const float4*)(Aptr + k0);
        float4 b4 = *(const float4*)(Bptr + k0);
        As[loadK + 0][loadRow] = a4.x;
        As[loadK + 1][loadRow] = a4.y;
        As[loadK + 2][loadRow] = a4.z;
        As[loadK + 3][loadRow] = a4.w;
        Bs[loadK + 0][loadRow] = b4.x;
        Bs[loadK + 1][loadRow] = b4.y;
        Bs[loadK + 2][loadRow] = b4.z;
        Bs[loadK + 3][loadRow] = b4.w;
        __syncthreads();
#pragma unroll
        for (int kk = 0; kk < BK; kk++) {
            float4 a0 = *(const float4*)&As[kk][ty * 8];
            float4 a1 = *(const float4*)&As[kk][ty * 8 + 4];
            float4 b0 = *(const float4*)&Bs[kk][tx * 8];
            float4 b1 = *(const float4*)&Bs[kk][tx * 8 + 4];
            float ar[8] = {a0.x, a0.y, a0.z, a0.w, a1.x, a1.y, a1.z, a1.w};
            float br[8] = {b0.x, b0.y, b0.z, b0.w, b1.x, b1.y, b1.z, b1.w};
#pragma unroll
            for (int i = 0; i < 8; i++)
#pragma unroll
                for (int j = 0; j < 8; j++) acc[i][j] = fmaf(ar[i], br[j], acc[i][j]);
        }
        __syncthreads();
    }

#pragma unroll
    for (int i = 0; i < 8; i++) {
        float* Crow = C + (size_t)(mBase + ty * 8 + i) * N + nBase + tx * 8;
        *(float4*)Crow = make_float4(acc[i][0], acc[i][1], acc[i][2], acc[i][3]);
        *(float4*)(Crow + 4) = make_float4(acc[i][4], acc[i][5], acc[i][6], acc[i][7]);
    }
}

// ---------------------------------------------------------------------------
// Kernel 3: conv + gating epilogue.
// proj[b, 0:H] = B_gate, proj[b, H:2H] = C_gate, proj[b, 2H:3H] = x.
// gated[b,h] = C_gate * (c0*w0 + c1*w1 + c2*w2 + (B_gate*x)*w3)
// out_state[idx[b], h, :] = {c1, c2, B_gate*x}
// ---------------------------------------------------------------------------
__global__ void conv_epilogue_kernel(const float* __restrict__ proj,
                                     const float* __restrict__ conv_state,
                                     const int* __restrict__ idx,
                                     const float* __restrict__ conv_w,
                                     float* __restrict__ gated,
                                     float* __restrict__ out_state) {
    int i = blockIdx.x * blockDim.x + threadIdx.x;
    if (i >= B_SZ * H_SZ) return;
    int b = i >> 11;           // / H_SZ
    int h = i & (H_SZ - 1);    // % H_SZ
    int r = idx[b];

    const float* cs = conv_state + ((size_t)r * H_SZ + h) * 3;
    float c0 = cs[0], c1 = cs[1], c2 = cs[2];

    const float* prow = proj + (size_t)b * 3 * H_SZ;
    float Bg = prow[h];
    float Cg = prow[H_SZ + h];
    float x  = prow[2 * H_SZ + h];
    float Bx = Bg * x;

    const float* w = conv_w + h * 4;
    float conv_out = fmaf(c0, w[0], fmaf(c1, w[1], fmaf(c2, w[2], Bx * w[3])));

    gated[i] = Cg * conv_out;

    float* os = out_state + ((size_t)r * H_SZ + h) * 3;
    os[0] = c1;
    os[1] = c2;
    os[2] = Bx;
}

// ---------------------------------------------------------------------------
extern "C" void kernel_launch(void* const* d_in, const int* in_sizes, int n_in,
                              void* d_out, int out_size) {
    const float* hidden     = (const float*)d_in[0];
    const float* conv_state = (const float*)d_in[1];
    const int*   idx        = (const int*)d_in[2];
    const float* w_in       = (const float*)d_in[3];
    const float* w_out      = (const float*)d_in[4];
    const float* conv_w     = (const float*)d_in[5];

    float* y         = (float*)d_out;
    float* out_state = y + (size_t)B_SZ * H_SZ;

    float *proj, *gated;
    cudaGetSymbolAddress((void**)&proj, g_proj);
    cudaGetSymbolAddress((void**)&gated, g_gated);

    // 1) copy conv_state through to the output (rows later overwritten)
    int n4 = (P_SZ * H_SZ * 3) / 4;
    copy_state_kernel<<<2048, 256>>>((const float4*)conv_state,
                                     (float4*)out_state, n4);

    // 2) proj = hidden @ w_in^T   [2048 x 6144]
    sgemm_nt_kernel<<<dim3((3 * H_SZ) / 128, B_SZ / 128), 256>>>(
        hidden, w_in, proj, B_SZ, 3 * H_SZ, H_SZ);

    // 3) conv + gate epilogue, scatter new state rows
    conv_epilogue_kernel<<<(B_SZ * H_SZ + 255) / 256, 256>>>(
        proj, conv_state, idx, conv_w, gated, out_state);

    // 4) y = gated @ w_out^T   [2048 x 2048]
    sgemm_nt_kernel<<<dim3(H_SZ / 128, B_SZ / 128), 256>>>(
        gated, w_out, y, B_SZ, H_SZ, H_SZ);
}